// round 4
// baseline (speedup 1.0000x reference)
#include <cuda_runtime.h>

// Correlation: out[b, di*9+dj, y, x] = (1/64) * sum_c f1[b,c,y,x] * f2pad[b,c,y+di,x+dj]
// f1,f2: [4,64,192,448] f32; out: [4,81,192,448] f32; D=4.
//
// Tile 64x4, block (8,4,9)=288 thr, thread owns 8 x-pixels + one di row (72 acc).
// Per channel/thread: 4 LDS.128 window + 2 LDS.128 f1 -> 72 FMA (1.33 B/MAC).
// 16B-chunk XOR swizzle (k ^ ((k>>3)&1)) makes the stride-8 window loads
// bank-conflict-free. cp.async 4-deep ring, CS=4 channels/stage.

#define D    4
#define CC   64
#define HH   192
#define WW   448
#define BB   4
#define XT   64
#define YT   4
#define NTX  8
#define NDJ  9
#define NDI  9
#define PWC  18               // f2 row chunks (72 floats)
#define PW   (PWC*4)          // 72
#define PH   (YT + 2*D)       // 12
#define F1C  (XT/4)           // 16 chunks per f1 row
#define CS   4
#define NSTAGE (CC / CS)      // 16
#define NTHREADS (NTX * YT * NDI)  // 288
#define RING 4

#define F2_STAGE_CHUNKS (CS*PH*PWC)   // 864 == 3*288
#define F1_STAGE_CHUNKS (CS*YT*F1C)   // 256
#define F2_STAGE_BYTES  (F2_STAGE_CHUNKS*16)  // 13824
#define STAGE_BYTES     ((F2_STAGE_CHUNKS + F1_STAGE_CHUNKS)*16)  // 17920
#define STAGE_FLOATS    (STAGE_BYTES/4)       // 4480
#define CSTRIDE ((size_t)CS * HH * WW * 4)    // global bytes per stage

__device__ __forceinline__ int swz(int k) { return k ^ ((k >> 3) & 1); }

__device__ __forceinline__ void cp_async16(unsigned saddr, const void* gaddr, int sz) {
    asm volatile("cp.async.cg.shared.global [%0], [%1], 16, %2;"
                 :: "r"(saddr), "l"(gaddr), "r"(sz));
}

__global__ __launch_bounds__(NTHREADS, 2)
void corr_kernel(const float* __restrict__ f1,
                 const float* __restrict__ f2,
                 float* __restrict__ out)
{
    extern __shared__ float smem[];   // RING * STAGE_FLOATS

    const int tx  = threadIdx.x;   // 0..7
    const int ty  = threadIdx.y;   // 0..3
    const int di  = threadIdx.z;   // 0..8  (warp == one di)
    const int tid = (di * YT + ty) * NTX + tx;

    const int x0 = blockIdx.x * XT;
    const int y0 = blockIdx.y * YT;
    const int b  = blockIdx.z;
    const int y  = y0 + ty;

    const char* f1b0 = (const char*)(f1 + (size_t)b * CC * HH * WW);
    const char* f2b0 = (const char*)(f2 + (size_t)b * CC * HH * WW);
    const unsigned sbase = (unsigned)__cvta_generic_to_shared(smem);

    // ---- writer chunks: k=0..2 -> f2 (c = tid + 288k, 0..863), k=3 -> f1 (c=tid<256)
    unsigned goff[4];
    unsigned soff[4];   // bit15 = valid (f2 only)
#pragma unroll
    for (int k = 0; k < 3; k++) {
        const int c   = tid + k * NTHREADS;
        const int cc  = c / (PH * PWC);
        const int rem = c - cc * (PH * PWC);
        const int r   = rem / PWC;
        const int h   = rem - r * PWC;
        const int gy  = y0 - D + r;
        const int gx  = x0 - D + 4 * h;
        const bool ok = ((unsigned)gy < HH) && ((unsigned)gx < WW);
        goff[k] = ok ? (unsigned)((cc * HH * WW + gy * WW + gx) * 4) : 0u;
        soff[k] = (unsigned)(((cc * PH + r) * PWC + swz(h)) * 16) | (ok ? 0x8000u : 0u);
    }
    const bool has4 = (tid < F1_STAGE_CHUNKS);
    {
        const int c2 = tid & (F1_STAGE_CHUNKS - 1);
        const int cc = c2 / (YT * F1C);
        const int rem = c2 - cc * (YT * F1C);
        const int r  = rem / F1C;
        const int h  = rem - r * F1C;
        goff[3] = (unsigned)((cc * HH * WW + (y0 + r) * WW + x0 + 4 * h) * 4);
        soff[3] = (unsigned)(F2_STAGE_BYTES + ((cc * YT + r) * F1C + swz(h)) * 16);
    }

    auto prefetch = [&](int s) {
        if (s < NSTAGE) {
            const size_t gadd = (size_t)s * CSTRIDE;
            const unsigned sb = sbase + (s & (RING - 1)) * STAGE_BYTES;
#pragma unroll
            for (int k = 0; k < 3; k++) {
                const int sz = (soff[k] & 0x8000u) ? 16 : 0;
                cp_async16(sb + (soff[k] & 0x7FFFu), f2b0 + goff[k] + gadd, sz);
            }
            if (has4) cp_async16(sb + soff[3], f1b0 + goff[3] + gadd, 16);
        }
        asm volatile("cp.async.commit_group;" ::: "memory");
    };

    // ---- reader base pointers (per-thread constant): swizzled chunk offsets
    const float* wp[4];
#pragma unroll
    for (int i = 0; i < 4; i++)
        wp[i] = smem + (ty + di) * PW + swz(2 * tx + i) * 4;
    const float* fp[2];
#pragma unroll
    for (int i = 0; i < 2; i++)
        fp[i] = smem + F2_STAGE_BYTES / 4 + ty * XT + swz(2 * tx + i) * 4;

    float acc[NDJ][8];
#pragma unroll
    for (int dj = 0; dj < NDJ; dj++)
#pragma unroll
        for (int xx = 0; xx < 8; xx++) acc[dj][xx] = 0.f;

    prefetch(0);
    prefetch(1);
    prefetch(2);

#pragma unroll 4
    for (int s = 0; s < NSTAGE; s++) {
        asm volatile("cp.async.wait_group 2;" ::: "memory");
        __syncthreads();

        const int roff = (s & (RING - 1)) * STAGE_FLOATS;

#pragma unroll
        for (int cc = 0; cc < CS; cc++) {
            float w[16];
            *(float4*)&w[0]  = *(const float4*)(wp[0] + roff + cc * (PH * PW));
            *(float4*)&w[4]  = *(const float4*)(wp[1] + roff + cc * (PH * PW));
            *(float4*)&w[8]  = *(const float4*)(wp[2] + roff + cc * (PH * PW));
            *(float4*)&w[12] = *(const float4*)(wp[3] + roff + cc * (PH * PW));
            float v1[8];
            *(float4*)&v1[0] = *(const float4*)(fp[0] + roff + cc * (YT * XT));
            *(float4*)&v1[4] = *(const float4*)(fp[1] + roff + cc * (YT * XT));
#pragma unroll
            for (int dj = 0; dj < NDJ; dj++)
#pragma unroll
                for (int xx = 0; xx < 8; xx++)
                    acc[dj][xx] += v1[xx] * w[dj + xx];
        }
        // next prefetch overwrites buffer (s-1)&3, fully consumed before this
        // iteration's barrier was passed by every thread.
        prefetch(s + 3);
    }

    const float scale = 1.f / (float)CC;
    float* ob = out + (((size_t)b * (NDI * NDJ) + di * NDJ) * HH + y) * WW + x0 + 8 * tx;
#pragma unroll
    for (int dj = 0; dj < NDJ; dj++) {
        float4 o0, o1;
        o0.x = acc[dj][0] * scale;  o0.y = acc[dj][1] * scale;
        o0.z = acc[dj][2] * scale;  o0.w = acc[dj][3] * scale;
        o1.x = acc[dj][4] * scale;  o1.y = acc[dj][5] * scale;
        o1.z = acc[dj][6] * scale;  o1.w = acc[dj][7] * scale;
        *(float4*)&ob[(size_t)dj * HH * WW]     = o0;
        *(float4*)&ob[(size_t)dj * HH * WW + 4] = o1;
    }
}

extern "C" void kernel_launch(void* const* d_in, const int* in_sizes, int n_in,
                              void* d_out, int out_size)
{
    const float* f1 = (const float*)d_in[0];
    const float* f2 = (const float*)d_in[1];
    float* out = (float*)d_out;

    cudaFuncSetAttribute(corr_kernel,
                         cudaFuncAttributeMaxDynamicSharedMemorySize,
                         RING * STAGE_BYTES);

    dim3 grid(WW / XT, HH / YT, BB);   // 7 x 48 x 4 = 1344 CTAs
    dim3 block(NTX, YT, NDI);          // 288 threads
    corr_kernel<<<grid, block, RING * STAGE_BYTES>>>(f1, f2, out);
}

// round 5
// speedup vs baseline: 1.7818x; 1.7818x over previous
#include <cuda_runtime.h>

// Correlation: out[b, di*9+dj, y, x] = (1/64) * sum_c f1[b,c,y,x] * f2pad[b,c,y+di,x+dj]
// f1,f2: [4,64,192,448] f32; out: [4,81,192,448] f32; D=4.
//
// R3 structure (119us): block (8,4,9)=288 thr, thread owns 4 x-pixels + one di row,
// 36 acc, cp.async 4-deep ring, CS=4 channels/stage, one barrier per stage.
// This round: inner loop packed as fma.rn.f32x2 (18 FFMA2 instead of 36 FFMA).

#define D    4
#define CC   64
#define HH   192
#define WW   448
#define BB   4
#define XT   32
#define YT   4
#define XPT  4
#define NTX  8
#define NDJ  9
#define NDI  9
#define PW   (XT + 2*D)      // 40
#define PH   (YT + 2*D)      // 12
#define CS   4               // channels per stage
#define NSTAGE (CC / CS)     // 16
#define NTHREADS (NTX * YT * NDI)  // 288
#define RING 4

#define F2_STAGE_FLOATS (CS*PH*PW)     // 1920
#define F1_STAGE_FLOATS (CS*YT*XT)     // 512
#define STAGE_FLOATS    (F2_STAGE_FLOATS + F1_STAGE_FLOATS)  // 2432
#define STAGE_BYTES     (STAGE_FLOATS * 4)                   // 9728

#define NCH_F2 (CS*PH*(PW/4))   // 480 16B chunks
#define NCH_F1 (CS*YT*(XT/4))   // 128 16B chunks
#define NCH    (NCH_F2 + NCH_F1) // 608
#define CSTRIDE_BYTES ((size_t)CS * HH * WW * 4)

typedef unsigned long long u64;

__device__ __forceinline__ void cp_async16(unsigned saddr, const void* gaddr, int sz) {
    asm volatile("cp.async.cg.shared.global [%0], [%1], 16, %2;"
                 :: "r"(saddr), "l"(gaddr), "r"(sz));
}
__device__ __forceinline__ u64 pk2(float lo, float hi) {
    u64 r; asm("mov.b64 %0, {%1, %2};" : "=l"(r) : "f"(lo), "f"(hi)); return r;
}
__device__ __forceinline__ void unpk(u64 v, float& lo, float& hi) {
    asm("mov.b64 {%0, %1}, %2;" : "=f"(lo), "=f"(hi) : "l"(v));
}
__device__ __forceinline__ void ffma2(u64& c, u64 a, u64 b) {
    asm("fma.rn.f32x2 %0, %1, %2, %0;" : "+l"(c) : "l"(a), "l"(b));
}
__device__ __forceinline__ u64 mul2(u64 a, u64 b) {
    u64 r; asm("mul.rn.f32x2 %0, %1, %2;" : "=l"(r) : "l"(a), "l"(b)); return r;
}

__global__ __launch_bounds__(NTHREADS, 3)
void corr_kernel(const float* __restrict__ f1,
                 const float* __restrict__ f2,
                 float* __restrict__ out)
{
    __shared__ float smem[RING * STAGE_FLOATS];   // 38912 B

    const int tx  = threadIdx.x;   // 0..7
    const int ty  = threadIdx.y;   // 0..3
    const int di  = threadIdx.z;   // 0..8
    const int tid = (di * YT + ty) * NTX + tx;

    const int x0 = blockIdx.x * XT;
    const int y0 = blockIdx.y * YT;
    const int b  = blockIdx.z;
    const int y  = y0 + ty;
    const int xp = tx * XPT;

    const float* f1b0 = f1 + (size_t)b * CC * HH * WW;
    const float* f2b0 = f2 + (size_t)b * CC * HH * WW;

    const unsigned sbase = (unsigned)__cvta_generic_to_shared(smem);

    // ---- precompute this thread's cp.async chunks (2 for all, 3rd for some) ----
    const char* ckp[2];
    unsigned    cks[2];
    int         ckz[2];
#pragma unroll
    for (int k = 0; k < 2; k++) {
        const int c = tid + k * NTHREADS;   // < 608 always
        if (c < NCH_F2) {
            const int cc = c / (PH * (PW/4));
            const int rem = c - cc * (PH * (PW/4));
            const int r  = rem / (PW/4);
            const int h  = rem - r * (PW/4);
            const int gy  = y0 - D + r;
            const int gxf = x0 - D + h * 4;
            const bool ok = ((unsigned)gy < HH) && ((unsigned)gxf < WW);
            ckp[k] = (const char*)(f2b0 + (size_t)cc * HH * WW
                                  + (ok ? ((size_t)gy * WW + gxf) : 0));
            ckz[k] = ok ? 16 : 0;
            cks[k] = ((cc * PH + r) * PW + h * 4) * 4;
        } else {
            const int c2 = c - NCH_F2;
            const int cc = c2 / (YT * (XT/4));
            const int rem = c2 - cc * (YT * (XT/4));
            const int r  = rem / (XT/4);
            const int h  = rem - r * (XT/4);
            ckp[k] = (const char*)(f1b0 + (size_t)cc * HH * WW
                                  + (size_t)(y0 + r) * WW + x0 + h * 4);
            ckz[k] = 16;
            cks[k] = F2_STAGE_FLOATS * 4 + ((cc * YT + r) * XT + h * 4) * 4;
        }
    }
    const bool has3 = (tid < NCH - 2 * NTHREADS);   // tid < 32
    const char* ck3p = nullptr; unsigned ck3s = 0;
    if (has3) {
        const int c  = tid + 2 * NTHREADS;    // 576..607 -> f1 region
        const int c2 = c - NCH_F2;            // 96..127
        const int cc = c2 / (YT * (XT/4));
        const int rem = c2 - cc * (YT * (XT/4));
        const int r  = rem / (XT/4);
        const int h  = rem - r * (XT/4);
        ck3p = (const char*)(f1b0 + (size_t)cc * HH * WW
                             + (size_t)(y0 + r) * WW + x0 + h * 4);
        ck3s = F2_STAGE_FLOATS * 4 + ((cc * YT + r) * XT + h * 4) * 4;
    }

    auto prefetch = [&](int s) {
        if (s < NSTAGE) {
            const size_t gadd = (size_t)s * CSTRIDE_BYTES;
            const unsigned sb = sbase + (s & (RING - 1)) * STAGE_BYTES;
            cp_async16(sb + cks[0], ckp[0] + gadd, ckz[0]);
            cp_async16(sb + cks[1], ckp[1] + gadd, ckz[1]);
            if (has3) cp_async16(sb + ck3s, ck3p + gadd, 16);
        }
        asm volatile("cp.async.commit_group;" ::: "memory");
    };

    // acc pairs: acc2[dj][0] = pixels (0,1), acc2[dj][1] = pixels (2,3)
    u64 acc2[NDJ][2];
    const u64 zz = pk2(0.f, 0.f);
#pragma unroll
    for (int dj = 0; dj < NDJ; dj++) { acc2[dj][0] = zz; acc2[dj][1] = zz; }

    prefetch(0);
    prefetch(1);
    prefetch(2);

#pragma unroll 4
    for (int s = 0; s < NSTAGE; s++) {
        asm volatile("cp.async.wait_group 2;" ::: "memory");
        __syncthreads();

        const float* f2t = smem + (s & (RING - 1)) * STAGE_FLOATS;
        const float* f1t = f2t + F2_STAGE_FLOATS;

#pragma unroll
        for (int cc = 0; cc < CS; cc++) {
            // f1 quad as two aligned f32x2 pairs
            const ulonglong2 v = *(const ulonglong2*)&f1t[(cc * YT + ty) * XT + xp];
            const u64 v01 = v.x, v23 = v.y;

            // window w[0..11] as three aligned pair-loads (LDS.128 each)
            const float* wrow = &f2t[(cc * PH + ty + di) * PW + xp];
            const ulonglong2 wa = *(const ulonglong2*)&wrow[0];  // p0=(w0,w1) p2=(w2,w3)
            const u64 wc8 = *(const u64*)&wrow[8];               // p8=(w8,w9)
            const u64 wcA = *(const u64*)&wrow[10];              // p10=(w10,w11)

            float w1,w2,w3,w4,w5,w6,w7,w8,w9,wA;
            unpk(wa.x, w1, w1);          // w1 = hi(wa.x)? -> careful: unpack both
            // full unpack of the middle region for odd pairs
            float l0,h0,l1,h1;
            unpk(wa.x, l0, h0);          // (w0,w1)
            unpk(wa.y, l1, h1);          // (w2,w3)
            const u64 wb0 = *(const u64*)&wrow[4];   // (w4,w5)
            const u64 wb1 = *(const u64*)&wrow[6];   // (w6,w7)
            float l2,h2,l3,h3,l4,h4,l5,h5;
            unpk(wb0, l2, h2);           // (w4,w5)
            unpk(wb1, l3, h3);           // (w6,w7)
            unpk(wc8, l4, h4);           // (w8,w9)
            unpk(wcA, l5, h5);           // (w10,w11)

            u64 p[11];
            p[0]  = wa.x;                // (w0,w1)
            p[2]  = wa.y;                // (w2,w3)
            p[4]  = wb0;                 // (w4,w5)
            p[6]  = wb1;                 // (w6,w7)
            p[8]  = wc8;                 // (w8,w9)
            p[10] = wcA;                 // (w10,w11)
            p[1]  = pk2(h0, l1);         // (w1,w2)
            p[3]  = pk2(h1, l2);         // (w3,w4)
            p[5]  = pk2(h2, l3);         // (w5,w6)
            p[7]  = pk2(h3, l4);         // (w7,w8)
            p[9]  = pk2(h4, l5);         // (w9,w10)

#pragma unroll
            for (int dj = 0; dj < NDJ; dj++) {
                ffma2(acc2[dj][0], v01, p[dj]);
                ffma2(acc2[dj][1], v23, p[dj + 2]);
            }
        }
        // next prefetch overwrites buffer (s-1)&3, fully consumed before this
        // iteration's barrier was passed by every thread.
        prefetch(s + 3);
    }

    const u64 sc2 = pk2(1.f / (float)CC, 1.f / (float)CC);
    float* ob = out + (((size_t)b * (NDI * NDJ) + di * NDJ) * HH + y) * WW + x0 + xp;
#pragma unroll
    for (int dj = 0; dj < NDJ; dj++) {
        ulonglong2 o;
        o.x = mul2(acc2[dj][0], sc2);
        o.y = mul2(acc2[dj][1], sc2);
        *(ulonglong2*)&ob[(size_t)dj * HH * WW] = o;
    }
}

extern "C" void kernel_launch(void* const* d_in, const int* in_sizes, int n_in,
                              void* d_out, int out_size)
{
    const float* f1 = (const float*)d_in[0];
    const float* f2 = (const float*)d_in[1];
    float* out = (float*)d_out;

    dim3 grid(WW / XT, HH / YT, BB);   // 14 x 48 x 4 = 2688 CTAs
    dim3 block(NTX, YT, NDI);          // 288 threads
    corr_kernel<<<grid, block>>>(f1, f2, out);
}